// round 16
// baseline (speedup 1.0000x reference)
#include <cuda_runtime.h>
#include <cuda_bf16.h>
#include <cuda_fp16.h>
#include <math.h>
#include <cstdint>

// Problem constants
#define Ld 4
#define Nn 2048
#define DIN 1024
#define Hh 8
#define DHd 64
#define INNER 512
#define DOUT 1024
#define SCALEF 0.125f   // 64^-0.5
#define LOG2E 1.44269504088896f

// ---------------------------------------------------------------------------
// Scratch (device globals)
// x, Wq/k/v, q, k, v: fp16 single; Wo, ao: bf16 hi/lo
// ---------------------------------------------------------------------------
__device__ __half        gxf[(size_t)Ld*Nn*DIN];
__device__ __half        gwqf[INNER*DIN], gwkf[INNER*DIN], gwvf[INNER*DIN];
__device__ __nv_bfloat16 gwoh[DOUT*INNER], gwol[DOUT*INNER];
__device__ __half        gqf[(size_t)Ld*Hh*Nn*DHd];
__device__ __half        gkf[(size_t)Ld*Hh*Nn*DHd];
__device__ __half        gvf[(size_t)Ld*Hh*Nn*DHd];
__device__ __nv_bfloat16 gaoh[(size_t)Ld*Nn*INNER], gaol[(size_t)Ld*Nn*INNER];
__device__ float g_bias[Ld*Nn];   // 0 or -1e9 (log2-domain bias)

// ===========================================================================
// Helpers
// ===========================================================================
__device__ __forceinline__ void mma_bf16(float* c, const uint32_t* a, const uint32_t* b) {
    asm volatile(
        "mma.sync.aligned.m16n8k16.row.col.f32.bf16.bf16.f32 "
        "{%0,%1,%2,%3}, {%4,%5,%6,%7}, {%8,%9}, {%0,%1,%2,%3};"
        : "+f"(c[0]), "+f"(c[1]), "+f"(c[2]), "+f"(c[3])
        : "r"(a[0]), "r"(a[1]), "r"(a[2]), "r"(a[3]), "r"(b[0]), "r"(b[1]));
}

__device__ __forceinline__ void mma_f16(float* c, const uint32_t* a, const uint32_t* b) {
    asm volatile(
        "mma.sync.aligned.m16n8k16.row.col.f32.f16.f16.f32 "
        "{%0,%1,%2,%3}, {%4,%5,%6,%7}, {%8,%9}, {%0,%1,%2,%3};"
        : "+f"(c[0]), "+f"(c[1]), "+f"(c[2]), "+f"(c[3])
        : "r"(a[0]), "r"(a[1]), "r"(a[2]), "r"(a[3]), "r"(b[0]), "r"(b[1]));
}

#define LDMX4(r, a) \
    asm volatile("ldmatrix.sync.aligned.m8n8.x4.shared.b16 {%0,%1,%2,%3}, [%4];" \
        : "=r"((r)[0]), "=r"((r)[1]), "=r"((r)[2]), "=r"((r)[3]) : "r"(a))

#define LDMX4T(r, a) \
    asm volatile("ldmatrix.sync.aligned.m8n8.x4.trans.shared.b16 {%0,%1,%2,%3}, [%4];" \
        : "=r"((r)[0]), "=r"((r)[1]), "=r"((r)[2]), "=r"((r)[3]) : "r"(a))

__device__ __forceinline__ uint32_t smem_to_u32(const void* p) {
    uint32_t a;
    asm("{ .reg .u64 t; cvta.to.shared.u64 t, %1; cvt.u32.u64 %0, t; }" : "=r"(a) : "l"(p));
    return a;
}

__device__ __forceinline__ void cp16(uint32_t s, const void* g) {
    asm volatile("cp.async.cg.shared.global [%0], [%1], 16;" :: "r"(s), "l"(g));
}
#define CP_COMMIT() asm volatile("cp.async.commit_group;" ::: "memory")
#define CP_WAIT1()  asm volatile("cp.async.wait_group 1;" ::: "memory")
#define CP_WAIT0()  asm volatile("cp.async.wait_group 0;" ::: "memory")

__device__ __forceinline__ float ex2f(float x) {
    float r;
    asm("ex2.approx.f32 %0, %1;" : "=f"(r) : "f"(x));
    return r;
}

// ===========================================================================
// Mask dtype detection + bias precompute
// ===========================================================================
__global__ void mask_convert_kernel(const unsigned char* __restrict__ raw) {
    __shared__ int flag_float, flag_big;
    int tid = threadIdx.x;
    if (tid == 0) { flag_float = 0; flag_big = 0; }
    __syncthreads();
    const unsigned int* w = (const unsigned int*)raw;
    for (int i = tid; i < 2048; i += blockDim.x) {
        unsigned int v = w[i];
        if (v == 0x3F800000u) atomicOr(&flag_float, 1);
        else if (v > 1u)      atomicOr(&flag_big, 1);
    }
    __syncthreads();
    bool isfloat = (flag_float != 0);
    bool isbyte  = (!isfloat) && (flag_big != 0);
    for (int i = tid; i < Ld*Nn; i += blockDim.x) {
        unsigned int v;
        if (isbyte) v = raw[i];
        else        v = ((const unsigned int*)raw)[i];
        g_bias[i] = (v != 0u) ? 0.0f : -1e9f;
    }
}

// ===========================================================================
// One-time conversions: x, Wq, Wk, Wv -> fp16;  Wo -> bf16 hi/lo
// ===========================================================================
#define NB_X  (Ld*Nn*DIN/4/256)
#define NB_W  (INNER*DIN/4/256)
__global__ void split_all_kernel(const float* __restrict__ x,
                                 const float* __restrict__ Wq,
                                 const float* __restrict__ Wk,
                                 const float* __restrict__ Wv,
                                 const float* __restrict__ Wo,
                                 __half* __restrict__ xf,
                                 __half* __restrict__ wqf,
                                 __half* __restrict__ wkf,
                                 __half* __restrict__ wvf,
                                 __nv_bfloat16* __restrict__ oh,
                                 __nv_bfloat16* __restrict__ ol) {
    int bid = blockIdx.x;
    if (bid < NB_X + 3*NB_W) {
        const float* in; __half* dst; int i;
        if (bid < NB_X) { in = x; dst = xf; i = bid*256 + threadIdx.x; }
        else {
            int wb = bid - NB_X;
            int which = wb / NB_W;
            i = (wb - which*NB_W)*256 + threadIdx.x;
            in  = (which == 0) ? Wq : (which == 1) ? Wk : Wv;
            dst = (which == 0) ? wqf : (which == 1) ? wkf : wvf;
        }
        float4 v = ((const float4*)in)[i];
        ((__half2*)dst)[i*2]   = __floats2half2_rn(v.x, v.y);
        ((__half2*)dst)[i*2+1] = __floats2half2_rn(v.z, v.w);
    } else {
        int i = (bid - NB_X - 3*NB_W)*256 + threadIdx.x;
        float4 v = ((const float4*)Wo)[i];
        __nv_bfloat16 h0 = __float2bfloat16_rn(v.x);
        __nv_bfloat16 h1 = __float2bfloat16_rn(v.y);
        __nv_bfloat16 h2 = __float2bfloat16_rn(v.z);
        __nv_bfloat16 h3 = __float2bfloat16_rn(v.w);
        ((__nv_bfloat162*)oh)[i*2]   = __halves2bfloat162(h0, h1);
        ((__nv_bfloat162*)oh)[i*2+1] = __halves2bfloat162(h2, h3);
        ((__nv_bfloat162*)ol)[i*2]   = __halves2bfloat162(
            __float2bfloat16_rn(v.x - __bfloat162float(h0)),
            __float2bfloat16_rn(v.y - __bfloat162float(h1)));
        ((__nv_bfloat162*)ol)[i*2+1] = __halves2bfloat162(
            __float2bfloat16_rn(v.z - __bfloat162float(h2)),
            __float2bfloat16_rn(v.w - __bfloat162float(h3)));
    }
}

// ===========================================================================
// fp16-single GEMM, 128x128 tile (QKV): halves x re-reads vs BN=64.
// 256 threads, 8 warps (4m x 2n), warp tile 32m x 64n, 64 fp32 accum regs.
// ===========================================================================
#define GF_ATS 72
#define GF_AELEMS (128 * GF_ATS)
#define GF_BELEMS (128 * GF_ATS)
#define GF_STAGE  (GF_AELEMS + GF_BELEMS)
#define GF_BYTES  (2 * GF_STAGE * 2)   // 73728

struct CFrag  { float c[2][4][4]; };
struct CFrag2 { float c[2][8][4]; };

__device__ __forceinline__ void gemm_f16_n128(
    const __half* __restrict__ A_g, int lda,
    const __half* __restrict__ B_g, int ldb,
    int Kdim, __half* sm, CFrag2& f)
{
    const int tid = threadIdx.x, lane = tid & 31, wid = tid >> 5;
    const int warp_m = wid >> 1, warp_n = wid & 1;
    const int lrow = lane & 15, lcol = (lane >> 4) << 3;
    const int brow = (lane & 7) + ((lane >> 3) & 1) * 8;

    const uint32_t smu = smem_to_u32(sm);

    #pragma unroll
    for (int mt = 0; mt < 2; mt++)
        #pragma unroll
        for (int nt = 0; nt < 8; nt++)
            #pragma unroll
            for (int i = 0; i < 4; i++) f.c[mt][nt][i] = 0.0f;

    auto issue = [&](int stg, int k0) {
        uint32_t sb = smu + (uint32_t)stg * (GF_STAGE * 2);
        #pragma unroll
        for (int it = 0; it < 4; it++) {
            int t = tid + it * 256;
            int r = t >> 3, cc = (t & 7) << 3;
            cp16(sb + (uint32_t)(r * GF_ATS + cc) * 2, A_g + (size_t)r * lda + k0 + cc);
            cp16(sb + (uint32_t)(GF_AELEMS + r * GF_ATS + cc) * 2,
                 B_g + (size_t)r * ldb + k0 + cc);
        }
    };

    const int nch = Kdim >> 6;
    issue(0, 0);
    CP_COMMIT();

    for (int c = 0; c < nch; c++) {
        if (c + 1 < nch) {
            issue((c + 1) & 1, (c + 1) << 6);
            CP_COMMIT();
            CP_WAIT1();
        } else {
            CP_WAIT0();
        }
        __syncthreads();

        const uint32_t sb = smu + (uint32_t)(c & 1) * (GF_STAGE * 2);
        const uint32_t a_u = sb;
        const uint32_t b_u = sb + GF_AELEMS * 2;

        #pragma unroll
        for (int ks = 0; ks < 4; ks++) {
            const int kk = ks * 16;
            uint32_t af[2][4];
            #pragma unroll
            for (int mt = 0; mt < 2; mt++)
                LDMX4(af[mt], a_u + (uint32_t)((warp_m*32 + mt*16 + lrow) * GF_ATS + kk + lcol) * 2);
            #pragma unroll
            for (int ng = 0; ng < 4; ng++) {
                uint32_t k4[4];
                LDMX4(k4, b_u + (uint32_t)((warp_n*64 + ng*16 + brow) * GF_ATS + kk + lcol) * 2);
                uint32_t b0[2] = {k4[0], k4[2]}, b1[2] = {k4[1], k4[3]};
                #pragma unroll
                for (int mt = 0; mt < 2; mt++) {
                    mma_f16(f.c[mt][ng*2],   af[mt], b0);
                    mma_f16(f.c[mt][ng*2+1], af[mt], b1);
                }
            }
        }
        __syncthreads();
    }
}

// ===========================================================================
// bf16 3-term GEMM (O-proj; validated config, 128x64)
// ===========================================================================
#define GS_ATS 72
#define GS_AELEMS (128 * GS_ATS)
#define GS_BELEMS (64 * GS_ATS)
#define GS_STAGE  (2 * GS_AELEMS + 2 * GS_BELEMS)
#define GS_BYTES  (2 * GS_STAGE * 2)

__device__ __forceinline__ void gemm_tc(
    const __nv_bfloat16* __restrict__ Ah_g, const __nv_bfloat16* __restrict__ Al_g, int lda,
    const __nv_bfloat16* __restrict__ Bh_g, const __nv_bfloat16* __restrict__ Bl_g, int ldb,
    int Kdim, __nv_bfloat16* sm, CFrag& f)
{
    const int tid = threadIdx.x, lane = tid & 31, wid = tid >> 5;
    const int warp_m = wid >> 1, warp_n = wid & 1;
    const int lrow = lane & 15, lcol = (lane >> 4) << 3;
    const int brow = (lane & 7) + ((lane >> 3) & 1) * 8;

    const uint32_t smu = smem_to_u32(sm);

    #pragma unroll
    for (int mt = 0; mt < 2; mt++)
        #pragma unroll
        for (int nt = 0; nt < 4; nt++)
            #pragma unroll
            for (int i = 0; i < 4; i++) f.c[mt][nt][i] = 0.0f;

    auto issue = [&](int stg, int k0) {
        uint32_t sb = smu + (uint32_t)stg * (GS_STAGE * 2);
        #pragma unroll
        for (int it = 0; it < 4; it++) {
            int t = tid + it * 256;
            int r = t >> 3, cc = (t & 7) << 3;
            uint32_t so = sb + (uint32_t)(r * GS_ATS + cc) * 2;
            cp16(so,                 Ah_g + (size_t)r * lda + k0 + cc);
            cp16(so + GS_AELEMS * 2, Al_g + (size_t)r * lda + k0 + cc);
        }
        #pragma unroll
        for (int it = 0; it < 2; it++) {
            int t = tid + it * 256;
            int r = t >> 3, cc = (t & 7) << 3;
            uint32_t so = sb + (uint32_t)(2 * GS_AELEMS + r * GS_ATS + cc) * 2;
            cp16(so,                 Bh_g + (size_t)r * ldb + k0 + cc);
            cp16(so + GS_BELEMS * 2, Bl_g + (size_t)r * ldb + k0 + cc);
        }
    };

    const int nch = Kdim >> 6;
    issue(0, 0);
    CP_COMMIT();

    for (int c = 0; c < nch; c++) {
        if (c + 1 < nch) {
            issue((c + 1) & 1, (c + 1) << 6);
            CP_COMMIT();
            CP_WAIT1();
        } else {
            CP_WAIT0();
        }
        __syncthreads();

        const uint32_t sb = smu + (uint32_t)(c & 1) * (GS_STAGE * 2);
        const uint32_t ah_u = sb;
        const uint32_t al_u = sb + GS_AELEMS * 2;
        const uint32_t bh_u = sb + 2 * GS_AELEMS * 2;
        const uint32_t bl_u = bh_u + GS_BELEMS * 2;

        #pragma unroll
        for (int ks = 0; ks < 4; ks++) {
            const int kk = ks * 16;
            uint32_t ahf[2][4], alf[2][4];
            #pragma unroll
            for (int mt = 0; mt < 2; mt++) {
                uint32_t off = (uint32_t)((warp_m*32 + mt*16 + lrow) * GS_ATS + kk + lcol) * 2;
                LDMX4(ahf[mt], ah_u + off);
                LDMX4(alf[mt], al_u + off);
            }
            #pragma unroll
            for (int ng = 0; ng < 2; ng++) {
                uint32_t off = (uint32_t)((warp_n*32 + ng*16 + brow) * GS_ATS + kk + lcol) * 2;
                uint32_t kh4[4], kl4[4];
                LDMX4(kh4, bh_u + off);
                LDMX4(kl4, bl_u + off);
                uint32_t b0h[2] = {kh4[0], kh4[2]}, b1h[2] = {kh4[1], kh4[3]};
                uint32_t b0l[2] = {kl4[0], kl4[2]}, b1l[2] = {kl4[1], kl4[3]};
                #pragma unroll
                for (int mt = 0; mt < 2; mt++) {
                    mma_bf16(f.c[mt][ng*2],   ahf[mt], b0h);
                    mma_bf16(f.c[mt][ng*2],   ahf[mt], b0l);
                    mma_bf16(f.c[mt][ng*2],   alf[mt], b0h);
                    mma_bf16(f.c[mt][ng*2+1], ahf[mt], b1h);
                    mma_bf16(f.c[mt][ng*2+1], ahf[mt], b1l);
                    mma_bf16(f.c[mt][ng*2+1], alf[mt], b1h);
                }
            }
        }
        __syncthreads();
    }
}

// ---------------------------------------------------------------------------
// QKV projection: 128x128 tile, two heads per CTA. q scaled by SCALEF*LOG2E.
// ---------------------------------------------------------------------------
__global__ __launch_bounds__(256, 2)
void qkv_tc_kernel() {
    extern __shared__ __half smf[];
    const int which = blockIdx.z;
    const __half* Wf = (which == 0) ? gwqf : (which == 1) ? gwkf : gwvf;
    __half* outf     = (which == 0) ? gqf  : (which == 1) ? gkf  : gvf;

    const int m0 = blockIdx.y * 128, e0 = blockIdx.x * 128;
    CFrag2 f;
    gemm_f16_n128(gxf + (size_t)m0 * DIN, DIN, Wf + (size_t)e0 * DIN, DIN, DIN, smf, f);

    const int tid = threadIdx.x, lane = tid & 31, wid = tid >> 5;
    const int gid = lane >> 2, tig = lane & 3;
    const int warp_m = wid >> 1, warp_n = wid & 1;
    const int head = blockIdx.x * 2 + warp_n;
    const float scale = (which == 0) ? (SCALEF * LOG2E) : 1.0f;

    #pragma unroll
    for (int mt = 0; mt < 2; mt++) {
        #pragma unroll
        for (int rr = 0; rr < 2; rr++) {
            int m = m0 + warp_m*32 + mt*16 + gid + rr*8;
            int l = m >> 11, n = m & 2047;
            __half* dstf = outf + ((size_t)((l*Hh + head)*Nn + n)) * DHd;
            #pragma unroll
            for (int nt = 0; nt < 8; nt++) {
                int d = nt*8 + tig*2;
                *(__half2*)(dstf + d) = __floats2half2_rn(
                    f.c[mt][nt][rr*2] * scale, f.c[mt][nt][rr*2+1] * scale);
            }
        }
    }
}

// ---------------------------------------------------------------------------
__global__ __launch_bounds__(256)
void oproj_tc_kernel(const float* __restrict__ bo, float* __restrict__ out) {
    extern __shared__ __nv_bfloat16 smg[];
    const int m0 = blockIdx.y * 128, o0 = blockIdx.x * 64;
    CFrag f;
    gemm_tc(gaoh + (size_t)m0 * INNER, gaol + (size_t)m0 * INNER, INNER,
            gwoh + (size_t)o0 * INNER, gwol + (size_t)o0 * INNER, INNER, INNER, smg, f);

    const int tid = threadIdx.x, lane = tid & 31, wid = tid >> 5;
    const int gid = lane >> 2, tig = lane & 3;
    const int warp_m = wid >> 1, warp_n = wid & 1;

    #pragma unroll
    for (int mt = 0; mt < 2; mt++) {
        #pragma unroll
        for (int rr = 0; rr < 2; rr++) {
            int m = m0 + warp_m*32 + mt*16 + gid + rr*8;
            float* dst = out + (size_t)m * DOUT + o0;
            #pragma unroll
            for (int nt = 0; nt < 4; nt++) {
                int col = warp_n*32 + nt*8 + tig*2;
                float2 b = *(const float2*)(bo + o0 + col);
                *(float2*)(dst + col) = make_float2(f.c[mt][nt][rr*2]   + b.x,
                                                    f.c[mt][nt][rr*2+1] + b.y);
            }
        }
    }
}

// ===========================================================================
// Flash attention: 128 q-rows per CTA (8 warps), fp16 path, log2 softmax,
// staggered cp.async K/V (amortized over 2x q-rows), bf16 hi/lo ao epilogue.
// ===========================================================================
#define ATS 72
#define A_TILE 4608
// Qf = 2 tiles (128 rows), Kf = 1, Vf = 1
#define A_SMEM_BYTES (4 * A_TILE * 2)   // 36864

__global__ __launch_bounds__(256, 2)
void attn_mma_kernel() {
    extern __shared__ char sb[];
    __half* Qf = (__half*)sb;                       // 128 x ATS
    __half* Kf = (__half*)sb + 2*A_TILE;            // 64 x ATS
    __half* Vf = (__half*)sb + 3*A_TILE;            // 64 x ATS

    const int qb = blockIdx.x, h = blockIdx.y, l = blockIdx.z;
    const int tid = threadIdx.x;
    const int wid = tid >> 5, lane = tid & 31;
    const int gid = lane >> 2, tig = lane & 3;
    const int q0 = qb * 128;
    const size_t hb = (size_t)((l*Hh + h) * Nn) * DHd;
    const float* __restrict__ brow_g = g_bias + l*Nn;

    const uint32_t kf_s = smem_to_u32(Kf);
    const uint32_t vf_s = smem_to_u32(Vf);

    auto issueK = [&](int kb) {
        #pragma unroll
        for (int it = 0; it < 2; it++) {
            int t = tid + it * 256;
            int r = t >> 3, c8 = (t & 7) << 3;
            cp16(kf_s + (uint32_t)(r*ATS + c8) * 2,
                 gkf + hb + (size_t)(kb*64 + r) * DHd + c8);
        }
    };
    auto issueV = [&](int kb) {
        #pragma unroll
        for (int it = 0; it < 2; it++) {
            int t = tid + it * 256;
            int r = t >> 3, c8 = (t & 7) << 3;
            cp16(vf_s + (uint32_t)(r*ATS + c8) * 2,
                 gvf + hb + (size_t)(kb*64 + r) * DHd + c8);
        }
    };

    issueK(0); CP_COMMIT();
    issueV(0); CP_COMMIT();

    // Load Q: 128 rows
    #pragma unroll
    for (int it = 0; it < 4; it++) {
        int t = tid + it * 256;
        int r = t >> 3, c8 = (t & 7) << 3;
        *(uint4*)(Qf + r*ATS + c8) = *(const uint4*)(gqf + hb + (size_t)(q0 + r)*DHd + c8);
    }

    const int lrow = lane & 15, lcol = (lane >> 4) << 3;
    const int brow = (lane & 7) + ((lane >> 3) & 1) * 8;
    const uint32_t qf_u = smem_to_u32(Qf);
    const int l4 = lane & 7, grp = lane >> 3;
    const int vrow = l4 + ((grp & 1) << 3);
    const int vcol = (grp >> 1) << 3;
    const uint32_t vf_base = vf_s + (uint32_t)(vrow * ATS + vcol) * 2;

    float o[8][4];
    #pragma unroll
    for (int nt = 0; nt < 8; nt++)
        #pragma unroll
        for (int i = 0; i < 4; i++) o[nt][i] = 0.0f;
    float m0 = -1e30f, m1 = -1e30f, l0 = 0.0f, l1 = 0.0f;

    for (int kb = 0; kb < Nn / 64; kb++) {
        CP_WAIT1();            // K(kb) ready
        __syncthreads();

        // ---- S = Q K^T (log2 domain; scale folded into q) ----
        float sfr[8][4];
        #pragma unroll
        for (int nt = 0; nt < 8; nt++)
            #pragma unroll
            for (int i = 0; i < 4; i++) sfr[nt][i] = 0.0f;

        #pragma unroll
        for (int ks = 0; ks < 4; ks++) {
            const int kk = ks * 16;
            uint32_t aq[4];
            LDMX4(aq, qf_u + (uint32_t)((wid*16 + lrow) * ATS + kk + lcol) * 2);
            #pragma unroll
            for (int ng = 0; ng < 4; ng++) {
                uint32_t kk4[4];
                LDMX4(kk4, kf_s + (uint32_t)((ng*16 + brow) * ATS + kk + lcol) * 2);
                uint32_t b0[2] = {kk4[0], kk4[2]}, b1[2] = {kk4[1], kk4[3]};
                mma_f16(sfr[ng*2],   aq, b0);
                mma_f16(sfr[ng*2+1], aq, b1);
            }
        }

        const float* bb = brow_g + kb*64;
        float mx0 = -1e30f, mx1 = -1e30f;
        #pragma unroll
        for (int nt = 0; nt < 8; nt++) {
            float2 b2 = *(const float2*)(bb + nt*8 + tig*2);
            sfr[nt][0] += b2.x; sfr[nt][1] += b2.y;
            sfr[nt][2] += b2.x; sfr[nt][3] += b2.y;
            mx0 = fmaxf(mx0, fmaxf(sfr[nt][0], sfr[nt][1]));
            mx1 = fmaxf(mx1, fmaxf(sfr[nt][2], sfr[nt][3]));
        }
        mx0 = fmaxf(mx0, __shfl_xor_sync(0xFFFFFFFFu, mx0, 1));
        mx0 = fmaxf(mx0, __shfl_xor_sync(0xFFFFFFFFu, mx0, 2));
        mx1 = fmaxf(mx1, __shfl_xor_sync(0xFFFFFFFFu, mx1, 1));
        mx1 = fmaxf(mx1, __shfl_xor_sync(0xFFFFFFFFu, mx1, 2));

        float mn0 = fmaxf(m0, mx0), mn1 = fmaxf(m1, mx1);
        float sc0 = ex2f(m0 - mn0), sc1 = ex2f(m1 - mn1);
        m0 = mn0; m1 = mn1;

        #pragma unroll
        for (int nt = 0; nt < 8; nt++) {
            o[nt][0] *= sc0; o[nt][1] *= sc0;
            o[nt][2] *= sc1; o[nt][3] *= sc1;
        }

        CP_WAIT0();            // V(kb) ready
        __syncthreads();       // V visible; all warps done with K(kb)
        if (kb + 1 < Nn/64) { issueK(kb + 1); CP_COMMIT(); }   // overlaps PV

        // ---- fused exp2/pack (fp16) + PV ----
        float rs0 = 0.0f, rs1 = 0.0f;
        #pragma unroll
        for (int ks = 0; ks < 4; ks++) {
            uint32_t ap[4];
            #pragma unroll
            for (int half = 0; half < 2; half++) {
                int nt = 2*ks + half;
                float p0 = ex2f(sfr[nt][0] - m0);
                float p1 = ex2f(sfr[nt][1] - m0);
                float p2 = ex2f(sfr[nt][2] - m1);
                float p3 = ex2f(sfr[nt][3] - m1);
                rs0 += p0 + p1; rs1 += p2 + p3;
                __half2 ph01 = __floats2half2_rn(p0, p1);
                __half2 ph23 = __floats2half2_rn(p2, p3);
                ap[half*2+0] = *reinterpret_cast<uint32_t*>(&ph01);
                ap[half*2+1] = *reinterpret_cast<uint32_t*>(&ph23);
            }
            #pragma unroll
            for (int dhc = 0; dhc < 4; dhc++) {
                uint32_t off = (uint32_t)(ks * 16 * ATS + dhc * 16) * 2;
                uint32_t bvf[4];
                LDMX4T(bvf, vf_base + off);
                mma_f16(o[dhc*2],   ap, bvf);
                mma_f16(o[dhc*2+1], ap, bvf + 2);
            }
        }
        rs0 += __shfl_xor_sync(0xFFFFFFFFu, rs0, 1);
        rs0 += __shfl_xor_sync(0xFFFFFFFFu, rs0, 2);
        rs1 += __shfl_xor_sync(0xFFFFFFFFu, rs1, 1);
        rs1 += __shfl_xor_sync(0xFFFFFFFFu, rs1, 2);
        l0 = l0 * sc0 + rs0;
        l1 = l1 * sc1 + rs1;

        __syncthreads();       // all warps done with V(kb)
        if (kb + 1 < Nn/64) { issueV(kb + 1); CP_COMMIT(); }   // overlaps next QK
    }

    // ---- epilogue: normalize, split hi/lo, write bf16 ao ----
    float inv0 = 1.0f / l0, inv1 = 1.0f / l1;
    int qr0 = q0 + wid*16 + gid;
    size_t b0i = (size_t)(l*Nn + qr0) * INNER + h*DHd;
    size_t b1i = (size_t)(l*Nn + qr0 + 8) * INNER + h*DHd;
    #pragma unroll
    for (int nt = 0; nt < 8; nt++) {
        int col = nt*8 + tig*2;
        float v0 = o[nt][0]*inv0, v1 = o[nt][1]*inv0;
        float v2 = o[nt][2]*inv1, v3 = o[nt][3]*inv1;
        __nv_bfloat16 h0 = __float2bfloat16_rn(v0), h1 = __float2bfloat16_rn(v1);
        __nv_bfloat16 h2 = __float2bfloat16_rn(v2), h3 = __float2bfloat16_rn(v3);
        *(__nv_bfloat162*)(gaoh + b0i + col) = __halves2bfloat162(h0, h1);
        *(__nv_bfloat162*)(gaol + b0i + col) = __halves2bfloat162(
            __float2bfloat16_rn(v0 - __bfloat162float(h0)),
            __float2bfloat16_rn(v1 - __bfloat162float(h1)));
        *(__nv_bfloat162*)(gaoh + b1i + col) = __halves2bfloat162(h2, h3);
        *(__nv_bfloat162*)(gaol + b1i + col) = __halves2bfloat162(
            __float2bfloat16_rn(v2 - __bfloat162float(h2)),
            __float2bfloat16_rn(v3 - __bfloat162float(h3)));
    }
}

// ---------------------------------------------------------------------------
extern "C" void kernel_launch(void* const* d_in, const int* in_sizes, int n_in,
                              void* d_out, int out_size) {
    const float* x  = (const float*)d_in[0];
    const float* Wq = (const float*)d_in[1];
    const float* Wk = (const float*)d_in[2];
    const float* Wv = (const float*)d_in[3];
    const float* Wo = (const float*)d_in[4];
    const float* bo = (const float*)d_in[5];
    const unsigned char* mask = (const unsigned char*)d_in[6];
    float* out = (float*)d_out;

    mask_convert_kernel<<<1, 256>>>(mask);

    __half *p_xf, *p_wqf, *p_wkf, *p_wvf;
    __nv_bfloat16 *p_woh, *p_wol;
    cudaGetSymbolAddress((void**)&p_xf, gxf);
    cudaGetSymbolAddress((void**)&p_wqf, gwqf);
    cudaGetSymbolAddress((void**)&p_wkf, gwkf);
    cudaGetSymbolAddress((void**)&p_wvf, gwvf);
    cudaGetSymbolAddress((void**)&p_woh, gwoh);
    cudaGetSymbolAddress((void**)&p_wol, gwol);

    split_all_kernel<<<NB_X + 4*NB_W, 256>>>(x, Wq, Wk, Wv, Wo,
        p_xf, p_wqf, p_wkf, p_wvf, p_woh, p_wol);

    cudaFuncSetAttribute(qkv_tc_kernel, cudaFuncAttributeMaxDynamicSharedMemorySize,
                         GF_BYTES);
    cudaFuncSetAttribute(oproj_tc_kernel, cudaFuncAttributeMaxDynamicSharedMemorySize,
                         GS_BYTES);
    cudaFuncSetAttribute(attn_mma_kernel, cudaFuncAttributeMaxDynamicSharedMemorySize,
                         A_SMEM_BYTES);

    qkv_tc_kernel<<<dim3(INNER/128, (Ld*Nn)/128, 3), 256, GF_BYTES>>>();

    attn_mma_kernel<<<dim3(Nn/128, Hh, Ld), 256, A_SMEM_BYTES>>>();

    oproj_tc_kernel<<<dim3(DOUT/64, (Ld*Nn)/128), 256, GS_BYTES>>>(bo, out);
}

// round 17
// speedup vs baseline: 1.1568x; 1.1568x over previous
#include <cuda_runtime.h>
#include <cuda_bf16.h>
#include <cuda_fp16.h>
#include <math.h>
#include <cstdint>

// Problem constants
#define Ld 4
#define Nn 2048
#define DIN 1024
#define Hh 8
#define DHd 64
#define INNER 512
#define DOUT 1024
#define SCALEF 0.125f   // 64^-0.5
#define LOG2E 1.44269504088896f
#define LO_SCALE 2048.0f
#define LO_INV (1.0f/2048.0f)

// ---------------------------------------------------------------------------
// Scratch (device globals)
// x, Wq/k/v, q, k, v, ao: fp16 single
// Wo: fp16 hi + scaled-lo (2-term)
// ---------------------------------------------------------------------------
__device__ __half gxf[(size_t)Ld*Nn*DIN];
__device__ __half gwqf[INNER*DIN], gwkf[INNER*DIN], gwvf[INNER*DIN];
__device__ __half gwof_h[DOUT*INNER], gwof_l[DOUT*INNER];
__device__ __half gqf[(size_t)Ld*Hh*Nn*DHd];
__device__ __half gkf[(size_t)Ld*Hh*Nn*DHd];
__device__ __half gvf[(size_t)Ld*Hh*Nn*DHd];
__device__ __half gaof[(size_t)Ld*Nn*INNER];
__device__ float g_bias[Ld*Nn];   // 0 or -1e9 (log2-domain bias)

// ===========================================================================
// Helpers
// ===========================================================================
__device__ __forceinline__ void mma_f16(float* c, const uint32_t* a, const uint32_t* b) {
    asm volatile(
        "mma.sync.aligned.m16n8k16.row.col.f32.f16.f16.f32 "
        "{%0,%1,%2,%3}, {%4,%5,%6,%7}, {%8,%9}, {%0,%1,%2,%3};"
        : "+f"(c[0]), "+f"(c[1]), "+f"(c[2]), "+f"(c[3])
        : "r"(a[0]), "r"(a[1]), "r"(a[2]), "r"(a[3]), "r"(b[0]), "r"(b[1]));
}

#define LDMX4(r, a) \
    asm volatile("ldmatrix.sync.aligned.m8n8.x4.shared.b16 {%0,%1,%2,%3}, [%4];" \
        : "=r"((r)[0]), "=r"((r)[1]), "=r"((r)[2]), "=r"((r)[3]) : "r"(a))

#define LDMX4T(r, a) \
    asm volatile("ldmatrix.sync.aligned.m8n8.x4.trans.shared.b16 {%0,%1,%2,%3}, [%4];" \
        : "=r"((r)[0]), "=r"((r)[1]), "=r"((r)[2]), "=r"((r)[3]) : "r"(a))

__device__ __forceinline__ uint32_t smem_to_u32(const void* p) {
    uint32_t a;
    asm("{ .reg .u64 t; cvta.to.shared.u64 t, %1; cvt.u32.u64 %0, t; }" : "=r"(a) : "l"(p));
    return a;
}

__device__ __forceinline__ void cp16(uint32_t s, const void* g) {
    asm volatile("cp.async.cg.shared.global [%0], [%1], 16;" :: "r"(s), "l"(g));
}
#define CP_COMMIT() asm volatile("cp.async.commit_group;" ::: "memory")
#define CP_WAIT1()  asm volatile("cp.async.wait_group 1;" ::: "memory")
#define CP_WAIT0()  asm volatile("cp.async.wait_group 0;" ::: "memory")

__device__ __forceinline__ float ex2f(float x) {
    float r;
    asm("ex2.approx.f32 %0, %1;" : "=f"(r) : "f"(x));
    return r;
}

// ===========================================================================
// Mask dtype detection + bias precompute
// ===========================================================================
__global__ void mask_convert_kernel(const unsigned char* __restrict__ raw) {
    __shared__ int flag_float, flag_big;
    int tid = threadIdx.x;
    if (tid == 0) { flag_float = 0; flag_big = 0; }
    __syncthreads();
    const unsigned int* w = (const unsigned int*)raw;
    for (int i = tid; i < 2048; i += blockDim.x) {
        unsigned int v = w[i];
        if (v == 0x3F800000u) atomicOr(&flag_float, 1);
        else if (v > 1u)      atomicOr(&flag_big, 1);
    }
    __syncthreads();
    bool isfloat = (flag_float != 0);
    bool isbyte  = (!isfloat) && (flag_big != 0);
    for (int i = tid; i < Ld*Nn; i += blockDim.x) {
        unsigned int v;
        if (isbyte) v = raw[i];
        else        v = ((const unsigned int*)raw)[i];
        g_bias[i] = (v != 0u) ? 0.0f : -1e9f;
    }
}

// ===========================================================================
// One-time conversions: x, Wq, Wk, Wv -> fp16;  Wo -> fp16 hi + scaled lo
// ===========================================================================
#define NB_X  (Ld*Nn*DIN/4/256)
#define NB_W  (INNER*DIN/4/256)
__global__ void split_all_kernel(const float* __restrict__ x,
                                 const float* __restrict__ Wq,
                                 const float* __restrict__ Wk,
                                 const float* __restrict__ Wv,
                                 const float* __restrict__ Wo,
                                 __half* __restrict__ xf,
                                 __half* __restrict__ wqf,
                                 __half* __restrict__ wkf,
                                 __half* __restrict__ wvf,
                                 __half* __restrict__ woh,
                                 __half* __restrict__ wol) {
    int bid = blockIdx.x;
    if (bid < NB_X + 3*NB_W) {
        const float* in; __half* dst; int i;
        if (bid < NB_X) { in = x; dst = xf; i = bid*256 + threadIdx.x; }
        else {
            int wb = bid - NB_X;
            int which = wb / NB_W;
            i = (wb - which*NB_W)*256 + threadIdx.x;
            in  = (which == 0) ? Wq : (which == 1) ? Wk : Wv;
            dst = (which == 0) ? wqf : (which == 1) ? wkf : wvf;
        }
        float4 v = ((const float4*)in)[i];
        ((__half2*)dst)[i*2]   = __floats2half2_rn(v.x, v.y);
        ((__half2*)dst)[i*2+1] = __floats2half2_rn(v.z, v.w);
    } else {
        int i = (bid - NB_X - 3*NB_W)*256 + threadIdx.x;
        float4 v = ((const float4*)Wo)[i];
        __half h0 = __float2half_rn(v.x);
        __half h1 = __float2half_rn(v.y);
        __half h2 = __float2half_rn(v.z);
        __half h3 = __float2half_rn(v.w);
        ((__half2*)woh)[i*2]   = __halves2half2(h0, h1);
        ((__half2*)woh)[i*2+1] = __halves2half2(h2, h3);
        ((__half2*)wol)[i*2]   = __floats2half2_rn(
            (v.x - __half2float(h0)) * LO_SCALE, (v.y - __half2float(h1)) * LO_SCALE);
        ((__half2*)wol)[i*2+1] = __floats2half2_rn(
            (v.z - __half2float(h2)) * LO_SCALE, (v.w - __half2float(h3)) * LO_SCALE);
    }
}

// ===========================================================================
// fp16-single GEMM (QKV): C[128 x 64] = A[128 x K]f16 * B[64 x K]f16^T
// (R15 config, validated)
// ===========================================================================
#define GF_ATS 72
#define GF_AELEMS (128 * GF_ATS)
#define GF_BELEMS (64 * GF_ATS)
#define GF_STAGE  (GF_AELEMS + GF_BELEMS)
#define GF_BYTES  (2 * GF_STAGE * 2)

struct CFrag { float c[2][4][4]; };

__device__ __forceinline__ void gemm_f16(
    const __half* __restrict__ A_g, int lda,
    const __half* __restrict__ B_g, int ldb,
    int Kdim, __half* sm, CFrag& f)
{
    const int tid = threadIdx.x, lane = tid & 31, wid = tid >> 5;
    const int warp_m = wid >> 1, warp_n = wid & 1;
    const int lrow = lane & 15, lcol = (lane >> 4) << 3;
    const int brow = (lane & 7) + ((lane >> 3) & 1) * 8;

    const uint32_t smu = smem_to_u32(sm);

    #pragma unroll
    for (int mt = 0; mt < 2; mt++)
        #pragma unroll
        for (int nt = 0; nt < 4; nt++)
            #pragma unroll
            for (int i = 0; i < 4; i++) f.c[mt][nt][i] = 0.0f;

    auto issue = [&](int stg, int k0) {
        uint32_t sb = smu + (uint32_t)stg * (GF_STAGE * 2);
        #pragma unroll
        for (int it = 0; it < 4; it++) {
            int t = tid + it * 256;
            int r = t >> 3, cc = (t & 7) << 3;
            cp16(sb + (uint32_t)(r * GF_ATS + cc) * 2, A_g + (size_t)r * lda + k0 + cc);
        }
        #pragma unroll
        for (int it = 0; it < 2; it++) {
            int t = tid + it * 256;
            int r = t >> 3, cc = (t & 7) << 3;
            cp16(sb + (uint32_t)(GF_AELEMS + r * GF_ATS + cc) * 2,
                 B_g + (size_t)r * ldb + k0 + cc);
        }
    };

    const int nch = Kdim >> 6;
    issue(0, 0);
    CP_COMMIT();

    for (int c = 0; c < nch; c++) {
        if (c + 1 < nch) {
            issue((c + 1) & 1, (c + 1) << 6);
            CP_COMMIT();
            CP_WAIT1();
        } else {
            CP_WAIT0();
        }
        __syncthreads();

        const uint32_t sb = smu + (uint32_t)(c & 1) * (GF_STAGE * 2);
        const uint32_t a_u = sb;
        const uint32_t b_u = sb + GF_AELEMS * 2;

        #pragma unroll
        for (int ks = 0; ks < 4; ks++) {
            const int kk = ks * 16;
            uint32_t af[2][4];
            #pragma unroll
            for (int mt = 0; mt < 2; mt++)
                LDMX4(af[mt], a_u + (uint32_t)((warp_m*32 + mt*16 + lrow) * GF_ATS + kk + lcol) * 2);
            #pragma unroll
            for (int ng = 0; ng < 2; ng++) {
                uint32_t k4[4];
                LDMX4(k4, b_u + (uint32_t)((warp_n*32 + ng*16 + brow) * GF_ATS + kk + lcol) * 2);
                uint32_t b0[2] = {k4[0], k4[2]}, b1[2] = {k4[1], k4[3]};
                #pragma unroll
                for (int mt = 0; mt < 2; mt++) {
                    mma_f16(f.c[mt][ng*2],   af[mt], b0);
                    mma_f16(f.c[mt][ng*2+1], af[mt], b1);
                }
            }
        }
        __syncthreads();
    }
}

// ===========================================================================
// 2-term scaled-lo fp16 GEMM (O-proj): C = A*(Bh + Bl/2048)^T, dual accum
// ===========================================================================
#define GO_ATS 72
#define GO_AELEMS (128 * GO_ATS)
#define GO_BELEMS (64 * GO_ATS)
#define GO_STAGE  (GO_AELEMS + 2 * GO_BELEMS)
#define GO_BYTES  (2 * GO_STAGE * 2)

__device__ __forceinline__ void gemm_o2(
    const __half* __restrict__ A_g, int lda,
    const __half* __restrict__ Bh_g, const __half* __restrict__ Bl_g, int ldb,
    int Kdim, __half* sm, CFrag& f1, CFrag& f2)
{
    const int tid = threadIdx.x, lane = tid & 31, wid = tid >> 5;
    const int warp_m = wid >> 1, warp_n = wid & 1;
    const int lrow = lane & 15, lcol = (lane >> 4) << 3;
    const int brow = (lane & 7) + ((lane >> 3) & 1) * 8;

    const uint32_t smu = smem_to_u32(sm);

    #pragma unroll
    for (int mt = 0; mt < 2; mt++)
        #pragma unroll
        for (int nt = 0; nt < 4; nt++)
            #pragma unroll
            for (int i = 0; i < 4; i++) { f1.c[mt][nt][i] = 0.0f; f2.c[mt][nt][i] = 0.0f; }

    auto issue = [&](int stg, int k0) {
        uint32_t sb = smu + (uint32_t)stg * (GO_STAGE * 2);
        #pragma unroll
        for (int it = 0; it < 4; it++) {
            int t = tid + it * 256;
            int r = t >> 3, cc = (t & 7) << 3;
            cp16(sb + (uint32_t)(r * GO_ATS + cc) * 2, A_g + (size_t)r * lda + k0 + cc);
        }
        #pragma unroll
        for (int it = 0; it < 2; it++) {
            int t = tid + it * 256;
            int r = t >> 3, cc = (t & 7) << 3;
            uint32_t so = sb + (uint32_t)(GO_AELEMS + r * GO_ATS + cc) * 2;
            cp16(so,                 Bh_g + (size_t)r * ldb + k0 + cc);
            cp16(so + GO_BELEMS * 2, Bl_g + (size_t)r * ldb + k0 + cc);
        }
    };

    const int nch = Kdim >> 6;
    issue(0, 0);
    CP_COMMIT();

    for (int c = 0; c < nch; c++) {
        if (c + 1 < nch) {
            issue((c + 1) & 1, (c + 1) << 6);
            CP_COMMIT();
            CP_WAIT1();
        } else {
            CP_WAIT0();
        }
        __syncthreads();

        const uint32_t sb = smu + (uint32_t)(c & 1) * (GO_STAGE * 2);
        const uint32_t a_u  = sb;
        const uint32_t bh_u = sb + GO_AELEMS * 2;
        const uint32_t bl_u = bh_u + GO_BELEMS * 2;

        #pragma unroll
        for (int ks = 0; ks < 4; ks++) {
            const int kk = ks * 16;
            uint32_t af[2][4];
            #pragma unroll
            for (int mt = 0; mt < 2; mt++)
                LDMX4(af[mt], a_u + (uint32_t)((warp_m*32 + mt*16 + lrow) * GO_ATS + kk + lcol) * 2);
            #pragma unroll
            for (int ng = 0; ng < 2; ng++) {
                uint32_t off = (uint32_t)((warp_n*32 + ng*16 + brow) * GO_ATS + kk + lcol) * 2;
                uint32_t kh4[4], kl4[4];
                LDMX4(kh4, bh_u + off);
                LDMX4(kl4, bl_u + off);
                uint32_t b0h[2] = {kh4[0], kh4[2]}, b1h[2] = {kh4[1], kh4[3]};
                uint32_t b0l[2] = {kl4[0], kl4[2]}, b1l[2] = {kl4[1], kl4[3]};
                #pragma unroll
                for (int mt = 0; mt < 2; mt++) {
                    mma_f16(f1.c[mt][ng*2],   af[mt], b0h);
                    mma_f16(f2.c[mt][ng*2],   af[mt], b0l);
                    mma_f16(f1.c[mt][ng*2+1], af[mt], b1h);
                    mma_f16(f2.c[mt][ng*2+1], af[mt], b1l);
                }
            }
        }
        __syncthreads();
    }
}

// ---------------------------------------------------------------------------
// QKV projection: q,k,v -> fp16. q scaled by SCALEF*LOG2E (log2-domain S).
// ---------------------------------------------------------------------------
__global__ __launch_bounds__(256)
void qkv_tc_kernel() {
    extern __shared__ __half smf[];
    const int which = blockIdx.z;
    const __half* Wf = (which == 0) ? gwqf : (which == 1) ? gwkf : gwvf;
    __half* outf     = (which == 0) ? gqf  : (which == 1) ? gkf  : gvf;

    const int m0 = blockIdx.y * 128, e0 = blockIdx.x * 64;
    const int head = blockIdx.x;
    CFrag f;
    gemm_f16(gxf + (size_t)m0 * DIN, DIN, Wf + (size_t)e0 * DIN, DIN, DIN, smf, f);

    const int tid = threadIdx.x, lane = tid & 31, wid = tid >> 5;
    const int gid = lane >> 2, tig = lane & 3;
    const int warp_m = wid >> 1, warp_n = wid & 1;
    const float scale = (which == 0) ? (SCALEF * LOG2E) : 1.0f;

    #pragma unroll
    for (int mt = 0; mt < 2; mt++) {
        #pragma unroll
        for (int rr = 0; rr < 2; rr++) {
            int m = m0 + warp_m*32 + mt*16 + gid + rr*8;
            int l = m >> 11, n = m & 2047;
            __half* dstf = outf + ((size_t)((l*Hh + head)*Nn + n)) * DHd;
            #pragma unroll
            for (int nt = 0; nt < 4; nt++) {
                int d = warp_n*32 + nt*8 + tig*2;
                *(__half2*)(dstf + d) = __floats2half2_rn(
                    f.c[mt][nt][rr*2] * scale, f.c[mt][nt][rr*2+1] * scale);
            }
        }
    }
}

// ---------------------------------------------------------------------------
__global__ __launch_bounds__(256)
void oproj_tc_kernel(const float* __restrict__ bo, float* __restrict__ out) {
    extern __shared__ __half smf[];
    const int m0 = blockIdx.y * 128, o0 = blockIdx.x * 64;
    CFrag f1, f2;
    gemm_o2(gaof + (size_t)m0 * INNER, INNER,
            gwof_h + (size_t)o0 * INNER, gwof_l + (size_t)o0 * INNER, INNER,
            INNER, smf, f1, f2);

    const int tid = threadIdx.x, lane = tid & 31, wid = tid >> 5;
    const int gid = lane >> 2, tig = lane & 3;
    const int warp_m = wid >> 1, warp_n = wid & 1;

    #pragma unroll
    for (int mt = 0; mt < 2; mt++) {
        #pragma unroll
        for (int rr = 0; rr < 2; rr++) {
            int m = m0 + warp_m*32 + mt*16 + gid + rr*8;
            float* dst = out + (size_t)m * DOUT + o0;
            #pragma unroll
            for (int nt = 0; nt < 4; nt++) {
                int col = warp_n*32 + nt*8 + tig*2;
                float2 b = *(const float2*)(bo + o0 + col);
                float v0 = fmaf(f2.c[mt][nt][rr*2],   LO_INV, f1.c[mt][nt][rr*2])   + b.x;
                float v1 = fmaf(f2.c[mt][nt][rr*2+1], LO_INV, f1.c[mt][nt][rr*2+1]) + b.y;
                *(float2*)(dst + col) = make_float2(v0, v1);
            }
        }
    }
}

// ===========================================================================
// Flash attention (R15 structure, validated): 64 q-rows, 128 threads,
// fp16 path, log2 softmax (raw EX2, unconditional rescale), staggered
// cp.async, fp16 ao epilogue.
// ===========================================================================
#define ATS 72
#define A_TILE 4608
#define A_SMEM_BYTES (3 * A_TILE * 2)

__global__ __launch_bounds__(128, 4)
void attn_mma_kernel() {
    extern __shared__ char sb[];
    __half* Qf = (__half*)sb;
    __half* Kf = (__half*)sb + A_TILE;
    __half* Vf = (__half*)sb + 2*A_TILE;

    const int qb = blockIdx.x, h = blockIdx.y, l = blockIdx.z;
    const int tid = threadIdx.x;
    const int wid = tid >> 5, lane = tid & 31;
    const int gid = lane >> 2, tig = lane & 3;
    const int q0 = qb * 64;
    const size_t hb = (size_t)((l*Hh + h) * Nn) * DHd;
    const float* __restrict__ brow_g = g_bias + l*Nn;

    const uint32_t kf_s = smem_to_u32(Kf);
    const uint32_t vf_s = smem_to_u32(Vf);

    auto issueK = [&](int kb) {
        #pragma unroll
        for (int it = 0; it < 4; it++) {
            int t = tid + it * 128;
            int r = t >> 3, c8 = (t & 7) << 3;
            cp16(kf_s + (uint32_t)(r*ATS + c8) * 2,
                 gkf + hb + (size_t)(kb*64 + r) * DHd + c8);
        }
    };
    auto issueV = [&](int kb) {
        #pragma unroll
        for (int it = 0; it < 4; it++) {
            int t = tid + it * 128;
            int r = t >> 3, c8 = (t & 7) << 3;
            cp16(vf_s + (uint32_t)(r*ATS + c8) * 2,
                 gvf + hb + (size_t)(kb*64 + r) * DHd + c8);
        }
    };

    issueK(0); CP_COMMIT();
    issueV(0); CP_COMMIT();

    #pragma unroll
    for (int it = 0; it < 4; it++) {
        int t = tid + it * 128;
        int r = t >> 3, c8 = (t & 7) << 3;
        *(uint4*)(Qf + r*ATS + c8) = *(const uint4*)(gqf + hb + (size_t)(q0 + r)*DHd + c8);
    }

    const int lrow = lane & 15, lcol = (lane >> 4) << 3;
    const int brow = (lane & 7) + ((lane >> 3) & 1) * 8;
    const uint32_t qf_u = smem_to_u32(Qf);
    const int l4 = lane & 7, grp = lane >> 3;
    const int vrow = l4 + ((grp & 1) << 3);
    const int vcol = (grp >> 1) << 3;
    const uint32_t vf_base = vf_s + (uint32_t)(vrow * ATS + vcol) * 2;

    float o[8][4];
    #pragma unroll
    for (int nt = 0; nt < 8; nt++)
        #pragma unroll
        for (int i = 0; i < 4; i++) o[nt][i] = 0.0f;
    float m0 = -1e30f, m1 = -1e30f, l0 = 0.0f, l1 = 0.0f;

    for (int kb = 0; kb < Nn / 64; kb++) {
        CP_WAIT1();
        __syncthreads();

        float sfr[8][4];
        #pragma unroll
        for (int nt = 0; nt < 8; nt++)
            #pragma unroll
            for (int i = 0; i < 4; i++) sfr[nt][i] = 0.0f;

        #pragma unroll
        for (int ks = 0; ks < 4; ks++) {
            const int kk = ks * 16;
            uint32_t aq[4];
            LDMX4(aq, qf_u + (uint32_t)((wid*16 + lrow) * ATS + kk + lcol) * 2);
            #pragma unroll
            for (int ng = 0; ng < 4; ng++) {
                uint32_t kk4[4];
                LDMX4(kk4, kf_s + (uint32_t)((ng*16 + brow) * ATS + kk + lcol) * 2);
                uint32_t b0[2] = {kk4[0], kk4[2]}, b1[2] = {kk4[1], kk4[3]};
                mma_f16(sfr[ng*2],   aq, b0);
                mma_f16(sfr[ng*2+1], aq, b1);
            }
        }

        const float* bb = brow_g + kb*64;
        float mx0 = -1e30f, mx1 = -1e30f;
        #pragma unroll
        for (int nt = 0; nt < 8; nt++) {
            float2 b2 = *(const float2*)(bb + nt*8 + tig*2);
            sfr[nt][0] += b2.x; sfr[nt][1] += b2.y;
            sfr[nt][2] += b2.x; sfr[nt][3] += b2.y;
            mx0 = fmaxf(mx0, fmaxf(sfr[nt][0], sfr[nt][1]));
            mx1 = fmaxf(mx1, fmaxf(sfr[nt][2], sfr[nt][3]));
        }
        mx0 = fmaxf(mx0, __shfl_xor_sync(0xFFFFFFFFu, mx0, 1));
        mx0 = fmaxf(mx0, __shfl_xor_sync(0xFFFFFFFFu, mx0, 2));
        mx1 = fmaxf(mx1, __shfl_xor_sync(0xFFFFFFFFu, mx1, 1));
        mx1 = fmaxf(mx1, __shfl_xor_sync(0xFFFFFFFFu, mx1, 2));

        float mn0 = fmaxf(m0, mx0), mn1 = fmaxf(m1, mx1);
        float sc0 = ex2f(m0 - mn0), sc1 = ex2f(m1 - mn1);
        m0 = mn0; m1 = mn1;

        #pragma unroll
        for (int nt = 0; nt < 8; nt++) {
            o[nt][0] *= sc0; o[nt][1] *= sc0;
            o[nt][2] *= sc1; o[nt][3] *= sc1;
        }

        CP_WAIT0();
        __syncthreads();
        if (kb + 1 < Nn/64) { issueK(kb + 1); CP_COMMIT(); }

        float rs0 = 0.0f, rs1 = 0.0f;
        #pragma unroll
        for (int ks = 0; ks < 4; ks++) {
            uint32_t ap[4];
            #pragma unroll
            for (int half = 0; half < 2; half++) {
                int nt = 2*ks + half;
                float p0 = ex2f(sfr[nt][0] - m0);
                float p1 = ex2f(sfr[nt][1] - m0);
                float p2 = ex2f(sfr[nt][2] - m1);
                float p3 = ex2f(sfr[nt][3] - m1);
                rs0 += p0 + p1; rs1 += p2 + p3;
                __half2 ph01 = __floats2half2_rn(p0, p1);
                __half2 ph23 = __floats2half2_rn(p2, p3);
                ap[half*2+0] = *reinterpret_cast<uint32_t*>(&ph01);
                ap[half*2+1] = *reinterpret_cast<uint32_t*>(&ph23);
            }
            #pragma unroll
            for (int dhc = 0; dhc < 4; dhc++) {
                uint32_t off = (uint32_t)(ks * 16 * ATS + dhc * 16) * 2;
                uint32_t bvf[4];
                LDMX4T(bvf, vf_base + off);
                mma_f16(o[dhc*2],   ap, bvf);
                mma_f16(o[dhc*2+1], ap, bvf + 2);
            }
        }
        rs0 += __shfl_xor_sync(0xFFFFFFFFu, rs0, 1);
        rs0 += __shfl_xor_sync(0xFFFFFFFFu, rs0, 2);
        rs1 += __shfl_xor_sync(0xFFFFFFFFu, rs1, 1);
        rs1 += __shfl_xor_sync(0xFFFFFFFFu, rs1, 2);
        l0 = l0 * sc0 + rs0;
        l1 = l1 * sc1 + rs1;

        __syncthreads();
        if (kb + 1 < Nn/64) { issueV(kb + 1); CP_COMMIT(); }
    }

    // ---- epilogue: normalize, write fp16 ao ----
    float inv0 = 1.0f / l0, inv1 = 1.0f / l1;
    int qr0 = q0 + wid*16 + gid;
    size_t b0i = (size_t)(l*Nn + qr0) * INNER + h*DHd;
    size_t b1i = (size_t)(l*Nn + qr0 + 8) * INNER + h*DHd;
    #pragma unroll
    for (int nt = 0; nt < 8; nt++) {
        int col = nt*8 + tig*2;
        *(__half2*)(gaof + b0i + col) = __floats2half2_rn(o[nt][0]*inv0, o[nt][1]*inv0);
        *(__half2*)(gaof + b1i + col) = __floats2half2_rn(o[nt][2]*inv1, o[nt][3]*inv1);
    }
}

// ---------------------------------------------------------------------------
extern "C" void kernel_launch(void* const* d_in, const int* in_sizes, int n_in,
                              void* d_out, int out_size) {
    const float* x  = (const float*)d_in[0];
    const float* Wq = (const float*)d_in[1];
    const float* Wk = (const float*)d_in[2];
    const float* Wv = (const float*)d_in[3];
    const float* Wo = (const float*)d_in[4];
    const float* bo = (const float*)d_in[5];
    const unsigned char* mask = (const unsigned char*)d_in[6];
    float* out = (float*)d_out;

    mask_convert_kernel<<<1, 256>>>(mask);

    __half *p_xf, *p_wqf, *p_wkf, *p_wvf, *p_woh, *p_wol;
    cudaGetSymbolAddress((void**)&p_xf, gxf);
    cudaGetSymbolAddress((void**)&p_wqf, gwqf);
    cudaGetSymbolAddress((void**)&p_wkf, gwkf);
    cudaGetSymbolAddress((void**)&p_wvf, gwvf);
    cudaGetSymbolAddress((void**)&p_woh, gwof_h);
    cudaGetSymbolAddress((void**)&p_wol, gwof_l);

    split_all_kernel<<<NB_X + 4*NB_W, 256>>>(x, Wq, Wk, Wv, Wo,
        p_xf, p_wqf, p_wkf, p_wvf, p_woh, p_wol);

    cudaFuncSetAttribute(qkv_tc_kernel, cudaFuncAttributeMaxDynamicSharedMemorySize,
                         GF_BYTES);
    cudaFuncSetAttribute(oproj_tc_kernel, cudaFuncAttributeMaxDynamicSharedMemorySize,
                         GO_BYTES);
    cudaFuncSetAttribute(attn_mma_kernel, cudaFuncAttributeMaxDynamicSharedMemorySize,
                         A_SMEM_BYTES);

    qkv_tc_kernel<<<dim3(INNER/64, (Ld*Nn)/128, 3), 256, GF_BYTES>>>();

    attn_mma_kernel<<<dim3(Nn/64, Hh, Ld), 128, A_SMEM_BYTES>>>();

    oproj_tc_kernel<<<dim3(DOUT/64, (Ld*Nn)/128), 256, GO_BYTES>>>(bo, out);
}